// round 1
// baseline (speedup 1.0000x reference)
#include <cuda_runtime.h>

#define BB 256
#define HH 224
#define WW 224
#define HW (HH*WW)          // 50176
#define PARTS 4
#define ROWS_PER_PART (HH/PARTS)   // 56
#define TILE_ROWS 16
#define SRC_ROWS 18
#define NTILES (HH/TILE_ROWS)      // 14

__device__ float g_partial[BB*PARTS];

__device__ __forceinline__ float clamp01(float v){ return fminf(fmaxf(v,0.0f),1.0f); }

// ---------------- Kernel 1: per-image mean of grayscale(clip(bf*img)) ----------------
__global__ void __launch_bounds__(256) mean_kernel(const float* __restrict__ img,
                                                   const float* __restrict__ u_jitter,
                                                   const float* __restrict__ u_bright)
{
    int b = blockIdx.y;
    int part = blockIdx.x;
    __shared__ float red[256];
    if (u_jitter[b] >= 0.8f) {           // mean unused for jitter-off images
        if (threadIdx.x == 0) g_partial[b*PARTS+part] = 0.0f;
        return;
    }
    float bf = 1.0f + (2.0f*u_bright[b] - 1.0f)*0.2f;
    const float* base = img + (size_t)b*3*HW;
    int p0 = part*ROWS_PER_PART*WW;
    float sum = 0.0f;
    for (int i = threadIdx.x; i < ROWS_PER_PART*WW; i += blockDim.x) {
        int p = p0 + i;
        float r  = clamp01(bf*base[p]);
        float g  = clamp01(bf*base[HW+p]);
        float bl = clamp01(bf*base[2*HW+p]);
        sum += 0.299f*r + 0.587f*g + 0.114f*bl;
    }
    red[threadIdx.x] = sum;
    __syncthreads();
    for (int s = 128; s > 0; s >>= 1) {
        if (threadIdx.x < s) red[threadIdx.x] += red[threadIdx.x+s];
        __syncthreads();
    }
    if (threadIdx.x == 0) g_partial[b*PARTS+part] = red[0];
}

// ---------------- color jitter for one pixel ----------------
__device__ __forceinline__ void jitter_px(float& r, float& g, float& bl,
                                          float bf, float cf, float sf,
                                          float mg, float hue)
{
    // brightness blend with zeros
    r = clamp01(bf*r); g = clamp01(bf*g); bl = clamp01(bf*bl);
    // contrast blend with mean gray
    float omcf = 1.0f - cf;
    r  = clamp01(cf*r  + omcf*mg);
    g  = clamp01(cf*g  + omcf*mg);
    bl = clamp01(cf*bl + omcf*mg);
    // saturation blend with per-pixel gray
    float gray = 0.299f*r + 0.587f*g + 0.114f*bl;
    float omsf = 1.0f - sf;
    r  = clamp01(sf*r  + omsf*gray);
    g  = clamp01(sf*g  + omsf*gray);
    bl = clamp01(sf*bl + omsf*gray);
    // hue rotate (RGB -> HSV -> shift -> RGB)
    float maxc = fmaxf(fmaxf(r,g),bl);
    float minc = fminf(fminf(r,g),bl);
    float v = maxc;
    float cr = maxc - minc;
    bool  eqc = (cr == 0.0f);
    float s = cr / (eqc ? 1.0f : maxc);
    float crd = eqc ? 1.0f : cr;
    float inv = 1.0f / crd;
    float rc = (maxc - r)*inv;
    float gc = (maxc - g)*inv;
    float bc = (maxc - bl)*inv;
    float h;
    if (maxc == r)      h = bc - gc;
    else if (maxc == g) h = 2.0f + rc - bc;
    else                h = 4.0f + gc - rc;
    h = h*(1.0f/6.0f) + 1.0f;
    h = h - floorf(h);
    h = h + hue;
    h = h - floorf(h);
    float h6 = h*6.0f;
    float fi = floorf(h6);
    float f  = h6 - fi;
    int   i  = ((int)fi) % 6;   // handles the h==1.0 rounding edge (fi==6 -> 0, f==0)
    float p = v*(1.0f - s);
    float q = v*(1.0f - s*f);
    float t = v*(1.0f - s*(1.0f - f));
    float r2 = (i==0) ? v : (i==1) ? q : (i==2||i==3) ? p : (i==4) ? t : v;
    float g2 = (i==0) ? t : (i==1||i==2) ? v : (i==3) ? q : p;
    float b2 = (i==0||i==1) ? p : (i==2) ? t : (i==3||i==4) ? v : q;
    r  = clamp01(r2);
    g  = clamp01(g2);
    bl = clamp01(b2);
}

// ---------------- Kernel 2: fused jitter + crop-resize ----------------
__global__ void __launch_bounds__(256) aug_kernel(const float* __restrict__ img,
                                                  const float* __restrict__ u_jitter,
                                                  const float* __restrict__ u_bright,
                                                  const float* __restrict__ u_contrast,
                                                  const float* __restrict__ u_sat,
                                                  const float* __restrict__ u_hue,
                                                  const float* __restrict__ u_crop,
                                                  const float* __restrict__ u_scale,
                                                  const float* __restrict__ u_top,
                                                  const float* __restrict__ u_left,
                                                  float* __restrict__ out)
{
    __shared__ float sm[3][SRC_ROWS][WW];   // 48384 B

    int b   = blockIdx.y;
    int ty0 = blockIdx.x * TILE_ROWS;

    bool jit = (u_jitter[b] < 0.8f);
    bool crp = (u_crop[b]   < 0.5f);

    float bf = 1.0f + (2.0f*u_bright[b]   - 1.0f)*0.2f;
    float cf = 1.0f + (2.0f*u_contrast[b] - 1.0f)*0.2f;
    float sf = 1.0f + (2.0f*u_sat[b]      - 1.0f)*0.2f;
    float hf = (2.0f*u_hue[b] - 1.0f)*0.05f;
    float mg = 0.0f;
    if (jit) {
        mg = (g_partial[b*PARTS+0] + g_partial[b*PARTS+1] +
              g_partial[b*PARTS+2] + g_partial[b*PARTS+3]) * (1.0f/(float)HW);
    }

    const float* src = img + (size_t)b*3*HW;
    float*       dst = out + (size_t)b*3*HW;

    if (!crp) {
        // output = jittered (or raw) input rows, identity geometry
        if (!jit) {
            const float4* s4 = (const float4*)src;
            float4*       d4 = (float4*)dst;
            #pragma unroll
            for (int c = 0; c < 3; c++) {
                int base = (c*HW + ty0*WW) >> 2;
                for (int i = threadIdx.x; i < (TILE_ROWS*WW)>>2; i += blockDim.x)
                    d4[base+i] = s4[base+i];
            }
        } else {
            for (int idx = threadIdx.x; idx < TILE_ROWS*WW; idx += blockDim.x) {
                int p = ty0*WW + idx;
                float r = src[p], g = src[HW+p], bl = src[2*HW+p];
                jitter_px(r,g,bl, bf,cf,sf,mg,hf);
                dst[p] = r; dst[HW+p] = g; dst[2*HW+p] = bl;
            }
        }
        return;
    }

    // ---- crop geometry: must match JAX fp32 op-for-op (floor decisions) ----
    float scale = __fadd_rn(0.85f, __fmul_rn((1.0f - 0.85f), u_scale[b]));
    float chf   = floorf(__fmul_rn(224.0f, scale));
    float cwf   = chf;   // H == W
    float hm    = __fadd_rn(__fsub_rn(224.0f, chf), 1.0f);
    float topf  = fminf(fmaxf(floorf(__fmul_rn(u_top[b],  hm)), 0.0f), 224.0f - chf);
    float leftf = fminf(fmaxf(floorf(__fmul_rn(u_left[b], hm)), 0.0f), 224.0f - cwf);

    const float inv224 = 1.0f/224.0f;

    // source row window for this tile (ys monotone in y; same formula as loop below)
    float ys0 = fminf(fmaxf(topf + ((float)ty0 + 0.5f)*chf*inv224 - 0.5f, 0.0f), 223.0f);
    int ry0 = (int)floorf(ys0);

    // ---- phase 1: load + jitter SRC_ROWS x 224 slab into smem ----
    for (int idx = threadIdx.x; idx < SRC_ROWS*WW; idx += blockDim.x) {
        int row = idx / WW;
        int col = idx - row*WW;
        int srow = min(ry0 + row, HH-1);
        int p = srow*WW + col;
        float r = src[p], g = src[HW+p], bl = src[2*HW+p];
        if (jit) jitter_px(r,g,bl, bf,cf,sf,mg,hf);
        sm[0][row][col] = r;
        sm[1][row][col] = g;
        sm[2][row][col] = bl;
    }
    __syncthreads();

    // ---- phase 2: bilinear sample 16x224 output tile from smem ----
    for (int idx = threadIdx.x; idx < TILE_ROWS*WW; idx += blockDim.x) {
        int oy = ty0 + idx / WW;
        int ox = idx - (idx / WW)*WW;
        float ys = fminf(fmaxf(topf  + ((float)oy + 0.5f)*chf*inv224 - 0.5f, 0.0f), 223.0f);
        float xs = fminf(fmaxf(leftf + ((float)ox + 0.5f)*cwf*inv224 - 0.5f, 0.0f), 223.0f);
        float y0f = floorf(ys), x0f = floorf(xs);
        float wy = ys - y0f,   wx = xs - x0f;
        int y0 = (int)y0f - ry0;
        int y1 = min((int)y0f + 1, HH-1) - ry0;
        int x0 = (int)x0f;
        int x1 = min(x0 + 1, WW-1);
        float omwx = 1.0f - wx, omwy = 1.0f - wy;
        int po = oy*WW + ox;
        #pragma unroll
        for (int c = 0; c < 3; c++) {
            float a = sm[c][y0][x0], bq = sm[c][y0][x1];
            float cq = sm[c][y1][x0], dq = sm[c][y1][x1];
            float row0 = omwx*a  + wx*bq;
            float row1 = omwx*cq + wx*dq;
            dst[c*HW + po] = omwy*row0 + wy*row1;
        }
    }
}

extern "C" void kernel_launch(void* const* d_in, const int* in_sizes, int n_in,
                              void* d_out, int out_size)
{
    const float* img        = (const float*)d_in[0];
    const float* u_jitter   = (const float*)d_in[1];
    const float* u_bright   = (const float*)d_in[2];
    const float* u_contrast = (const float*)d_in[3];
    const float* u_sat      = (const float*)d_in[4];
    const float* u_hue      = (const float*)d_in[5];
    const float* u_crop     = (const float*)d_in[6];
    const float* u_scale    = (const float*)d_in[7];
    const float* u_top      = (const float*)d_in[8];
    const float* u_left     = (const float*)d_in[9];
    float* out = (float*)d_out;

    dim3 g1(PARTS, BB);
    mean_kernel<<<g1, 256>>>(img, u_jitter, u_bright);

    dim3 g2(NTILES, BB);
    aug_kernel<<<g2, 256>>>(img, u_jitter, u_bright, u_contrast, u_sat, u_hue,
                            u_crop, u_scale, u_top, u_left, out);
}

// round 2
// speedup vs baseline: 1.2030x; 1.2030x over previous
#include <cuda_runtime.h>

#define BB 256
#define HH 224
#define WW 224
#define HW (HH*WW)          // 50176
#define W4 (WW/4)           // 56
#define PARTS 4
#define ROWS_PER_PART (HH/PARTS)   // 56
#define TILE_ROWS 8
#define SRC_ROWS 10
#define NTILES (HH/TILE_ROWS)      // 28

__device__ float g_partial[BB*PARTS];

__device__ __forceinline__ float clamp01(float v){ return fminf(fmaxf(v,0.0f),1.0f); }

// ---------------- Kernel 1: per-image mean of grayscale(clip(bf*img)) ----------------
__global__ void __launch_bounds__(256) mean_kernel(const float* __restrict__ img,
                                                   const float* __restrict__ u_jitter,
                                                   const float* __restrict__ u_bright)
{
    int b = blockIdx.y;
    int part = blockIdx.x;
    __shared__ float red[256];
    if (u_jitter[b] >= 0.8f) {           // mean unused for jitter-off images
        if (threadIdx.x == 0) g_partial[b*PARTS+part] = 0.0f;
        return;
    }
    float bf = 1.0f + (2.0f*u_bright[b] - 1.0f)*0.2f;
    const float4* base = (const float4*)(img + (size_t)b*3*HW);
    int p0 = (part*ROWS_PER_PART*WW) >> 2;
    const int N4 = (ROWS_PER_PART*WW) >> 2;   // 3136
    float sum = 0.0f;
    for (int i = threadIdx.x; i < N4; i += blockDim.x) {
        int p = p0 + i;
        float4 r4 = base[p];
        float4 g4 = base[(HW>>2)+p];
        float4 b4 = base[(2*(HW>>2))+p];
        #pragma unroll
        for (int j = 0; j < 4; j++) {
            float r  = clamp01(bf*((const float*)&r4)[j]);
            float g  = clamp01(bf*((const float*)&g4)[j]);
            float bl = clamp01(bf*((const float*)&b4)[j]);
            sum += 0.299f*r + 0.587f*g + 0.114f*bl;
        }
    }
    red[threadIdx.x] = sum;
    __syncthreads();
    for (int s = 128; s > 0; s >>= 1) {
        if (threadIdx.x < s) red[threadIdx.x] += red[threadIdx.x+s];
        __syncthreads();
    }
    if (threadIdx.x == 0) g_partial[b*PARTS+part] = red[0];
}

// ---------------- color jitter for one pixel ----------------
__device__ __forceinline__ void jitter_px(float& r, float& g, float& bl,
                                          float bf, float cf, float sf,
                                          float mg, float hue)
{
    // brightness blend with zeros
    r = clamp01(bf*r); g = clamp01(bf*g); bl = clamp01(bf*bl);
    // contrast blend with mean gray
    float omcf = 1.0f - cf;
    r  = clamp01(cf*r  + omcf*mg);
    g  = clamp01(cf*g  + omcf*mg);
    bl = clamp01(cf*bl + omcf*mg);
    // saturation blend with per-pixel gray
    float gray = 0.299f*r + 0.587f*g + 0.114f*bl;
    float omsf = 1.0f - sf;
    r  = clamp01(sf*r  + omsf*gray);
    g  = clamp01(sf*g  + omsf*gray);
    bl = clamp01(sf*bl + omsf*gray);
    // hue rotate (RGB -> HSV -> shift -> RGB)
    float maxc = fmaxf(fmaxf(r,g),bl);
    float minc = fminf(fminf(r,g),bl);
    float v = maxc;
    float cr = maxc - minc;
    bool  eqc = (cr == 0.0f);
    float s = cr / (eqc ? 1.0f : maxc);
    float crd = eqc ? 1.0f : cr;
    float inv = 1.0f / crd;
    float rc = (maxc - r)*inv;
    float gc = (maxc - g)*inv;
    float bc = (maxc - bl)*inv;
    float h;
    if (maxc == r)      h = bc - gc;
    else if (maxc == g) h = 2.0f + rc - bc;
    else                h = 4.0f + gc - rc;
    h = h*(1.0f/6.0f) + 1.0f;
    h = h - floorf(h);
    h = h + hue;
    h = h - floorf(h);
    float h6 = h*6.0f;
    float fi = floorf(h6);
    float f  = h6 - fi;
    int   i  = ((int)fi) % 6;   // handles the h==1.0 rounding edge
    float p = v*(1.0f - s);
    float q = v*(1.0f - s*f);
    float t = v*(1.0f - s*(1.0f - f));
    float r2 = (i==0) ? v : (i==1) ? q : (i==2||i==3) ? p : (i==4) ? t : v;
    float g2 = (i==0) ? t : (i==1||i==2) ? v : (i==3) ? q : p;
    float b2 = (i==0||i==1) ? p : (i==2) ? t : (i==3||i==4) ? v : q;
    r  = clamp01(r2);
    g  = clamp01(g2);
    bl = clamp01(b2);
}

// ---------------- Kernel 2: fused jitter + crop-resize ----------------
__global__ void __launch_bounds__(256) aug_kernel(const float* __restrict__ img,
                                                  const float* __restrict__ u_jitter,
                                                  const float* __restrict__ u_bright,
                                                  const float* __restrict__ u_contrast,
                                                  const float* __restrict__ u_sat,
                                                  const float* __restrict__ u_hue,
                                                  const float* __restrict__ u_crop,
                                                  const float* __restrict__ u_scale,
                                                  const float* __restrict__ u_top,
                                                  const float* __restrict__ u_left,
                                                  float* __restrict__ out)
{
    __shared__ float sm[3][SRC_ROWS][WW];   // 26880 B

    int b   = blockIdx.y;
    int ty0 = blockIdx.x * TILE_ROWS;

    bool jit = (u_jitter[b] < 0.8f);
    bool crp = (u_crop[b]   < 0.5f);

    float bf = 1.0f + (2.0f*u_bright[b]   - 1.0f)*0.2f;
    float cf = 1.0f + (2.0f*u_contrast[b] - 1.0f)*0.2f;
    float sf = 1.0f + (2.0f*u_sat[b]      - 1.0f)*0.2f;
    float hf = (2.0f*u_hue[b] - 1.0f)*0.05f;
    float mg = 0.0f;
    if (jit) {
        mg = (g_partial[b*PARTS+0] + g_partial[b*PARTS+1] +
              g_partial[b*PARTS+2] + g_partial[b*PARTS+3]) * (1.0f/(float)HW);
    }

    const float* src = img + (size_t)b*3*HW;
    float*       dst = out + (size_t)b*3*HW;

    if (!crp) {
        // output = jittered (or raw) input rows, identity geometry
        const float4* s4 = (const float4*)src;
        float4*       d4 = (float4*)dst;
        if (!jit) {
            #pragma unroll
            for (int c = 0; c < 3; c++) {
                int base = (c*HW + ty0*WW) >> 2;
                for (int i = threadIdx.x; i < (TILE_ROWS*WW)>>2; i += blockDim.x)
                    d4[base+i] = s4[base+i];
            }
        } else {
            int base = (ty0*WW) >> 2;
            for (int i = threadIdx.x; i < (TILE_ROWS*WW)>>2; i += blockDim.x) {
                int p = base + i;
                float4 r4 = s4[p];
                float4 g4 = s4[(HW>>2)+p];
                float4 b4 = s4[(2*(HW>>2))+p];
                #pragma unroll
                for (int j = 0; j < 4; j++) {
                    float r  = ((const float*)&r4)[j];
                    float g  = ((const float*)&g4)[j];
                    float bl = ((const float*)&b4)[j];
                    jitter_px(r,g,bl, bf,cf,sf,mg,hf);
                    ((float*)&r4)[j] = r; ((float*)&g4)[j] = g; ((float*)&b4)[j] = bl;
                }
                d4[p] = r4;
                d4[(HW>>2)+p] = g4;
                d4[(2*(HW>>2))+p] = b4;
            }
        }
        return;
    }

    // ---- crop geometry: must match JAX fp32 op-for-op (floor decisions) ----
    float scale = __fadd_rn(0.85f, __fmul_rn((1.0f - 0.85f), u_scale[b]));
    float chf   = floorf(__fmul_rn(224.0f, scale));
    float cwf   = chf;   // H == W
    float hm    = __fadd_rn(__fsub_rn(224.0f, chf), 1.0f);
    float topf  = fminf(fmaxf(floorf(__fmul_rn(u_top[b],  hm)), 0.0f), 224.0f - chf);
    float leftf = fminf(fmaxf(floorf(__fmul_rn(u_left[b], hm)), 0.0f), 224.0f - cwf);

    const float inv224 = 1.0f/224.0f;

    // source row window for this tile (ys monotone in y; same formula as loop below)
    float ys0 = fminf(fmaxf(topf + ((float)ty0 + 0.5f)*chf*inv224 - 0.5f, 0.0f), 223.0f);
    int ry0 = (int)floorf(ys0);

    // ---- phase 1: load + jitter SRC_ROWS x 224 slab into smem ----
    for (int idx = threadIdx.x; idx < SRC_ROWS*WW; idx += blockDim.x) {
        int row = idx / WW;
        int col = idx - row*WW;
        int srow = min(ry0 + row, HH-1);
        int p = srow*WW + col;
        float r = src[p], g = src[HW+p], bl = src[2*HW+p];
        if (jit) jitter_px(r,g,bl, bf,cf,sf,mg,hf);
        sm[0][row][col] = r;
        sm[1][row][col] = g;
        sm[2][row][col] = bl;
    }
    __syncthreads();

    // ---- phase 2: bilinear sample TILE_ROWS x 224 output, 4 px per thread ----
    for (int idx = threadIdx.x; idx < TILE_ROWS*W4; idx += blockDim.x) {
        int ry = idx / W4;
        int c4 = idx - ry*W4;
        int oy = ty0 + ry;
        float ys = fminf(fmaxf(topf + ((float)oy + 0.5f)*chf*inv224 - 0.5f, 0.0f), 223.0f);
        float y0f = floorf(ys);
        float wy  = ys - y0f;
        float omwy = 1.0f - wy;
        int y0 = (int)y0f - ry0;
        int y1 = min((int)y0f + 1, HH-1) - ry0;

        int   x0[4], x1[4];
        float wx[4];
        #pragma unroll
        for (int j = 0; j < 4; j++) {
            int ox = c4*4 + j;
            float xs = fminf(fmaxf(leftf + ((float)ox + 0.5f)*cwf*inv224 - 0.5f, 0.0f), 223.0f);
            float x0f = floorf(xs);
            wx[j] = xs - x0f;
            x0[j] = (int)x0f;
            x1[j] = min(x0[j] + 1, WW-1);
        }

        float4* d4 = (float4*)dst;
        int po4 = oy*W4 + c4;
        #pragma unroll
        for (int c = 0; c < 3; c++) {
            float4 o;
            #pragma unroll
            for (int j = 0; j < 4; j++) {
                float a  = sm[c][y0][x0[j]], bq = sm[c][y0][x1[j]];
                float cq = sm[c][y1][x0[j]], dq = sm[c][y1][x1[j]];
                float omwx = 1.0f - wx[j];
                float row0 = omwx*a  + wx[j]*bq;
                float row1 = omwx*cq + wx[j]*dq;
                ((float*)&o)[j] = omwy*row0 + wy*row1;
            }
            d4[c*(HW>>2) + po4] = o;
        }
    }
}

extern "C" void kernel_launch(void* const* d_in, const int* in_sizes, int n_in,
                              void* d_out, int out_size)
{
    const float* img        = (const float*)d_in[0];
    const float* u_jitter   = (const float*)d_in[1];
    const float* u_bright   = (const float*)d_in[2];
    const float* u_contrast = (const float*)d_in[3];
    const float* u_sat      = (const float*)d_in[4];
    const float* u_hue      = (const float*)d_in[5];
    const float* u_crop     = (const float*)d_in[6];
    const float* u_scale    = (const float*)d_in[7];
    const float* u_top      = (const float*)d_in[8];
    const float* u_left     = (const float*)d_in[9];
    float* out = (float*)d_out;

    dim3 g1(PARTS, BB);
    mean_kernel<<<g1, 256>>>(img, u_jitter, u_bright);

    dim3 g2(NTILES, BB);
    aug_kernel<<<g2, 256>>>(img, u_jitter, u_bright, u_contrast, u_sat, u_hue,
                            u_crop, u_scale, u_top, u_left, out);
}

// round 4
// speedup vs baseline: 1.2972x; 1.0783x over previous
#include <cuda_runtime.h>

#define BB 256
#define HH 224
#define WW 224
#define HW (HH*WW)          // 50176
#define W4 (WW/4)           // 56
#define PARTS 8
#define ROWS_PER_PART (HH/PARTS)   // 28
#define TILE_ROWS 8
#define SRC_ROWS 9
#define NTILES (HH/TILE_ROWS)      // 28

__device__ float g_partial[BB*PARTS];

// ---------------- Kernel 1: per-image mean of grayscale(clip(bf*img)) ----------------
__global__ void __launch_bounds__(256) mean_kernel(const float* __restrict__ img,
                                                   const float* __restrict__ u_jitter,
                                                   const float* __restrict__ u_bright)
{
    int b = blockIdx.y;
    int part = blockIdx.x;
    __shared__ float red[256];
    if (u_jitter[b] >= 0.8f) {           // mean unused for jitter-off images
        if (threadIdx.x == 0) g_partial[b*PARTS+part] = 0.0f;
        return;
    }
    float bf = 1.0f + (2.0f*u_bright[b] - 1.0f)*0.2f;
    const float4* base = (const float4*)(img + (size_t)b*3*HW);
    int p0 = (part*ROWS_PER_PART*WW) >> 2;
    const int N4 = (ROWS_PER_PART*WW) >> 2;
    float sum = 0.0f;
    for (int i = threadIdx.x; i < N4; i += blockDim.x) {
        int p = p0 + i;
        float4 r4 = base[p];
        float4 g4 = base[(HW>>2)+p];
        float4 b4 = base[(2*(HW>>2))+p];
        #pragma unroll
        for (int j = 0; j < 4; j++) {
            float r  = __saturatef(bf*((const float*)&r4)[j]);
            float g  = __saturatef(bf*((const float*)&g4)[j]);
            float bl = __saturatef(bf*((const float*)&b4)[j]);
            sum += 0.299f*r + 0.587f*g + 0.114f*bl;
        }
    }
    red[threadIdx.x] = sum;
    __syncthreads();
    for (int s = 128; s > 0; s >>= 1) {
        if (threadIdx.x < s) red[threadIdx.x] += red[threadIdx.x+s];
        __syncthreads();
    }
    if (threadIdx.x == 0) g_partial[b*PARTS+part] = red[0];
}

// ---------------- color jitter for one pixel ----------------
__device__ __forceinline__ void jitter_px(float& r, float& g, float& bl,
                                          float bf, float cf, float sf,
                                          float mg, float hue)
{
    // brightness blend with zeros (saturate folds into the MUL)
    r = __saturatef(bf*r); g = __saturatef(bf*g); bl = __saturatef(bf*bl);
    // contrast blend with mean gray
    float cm = (1.0f - cf)*mg;
    r  = __saturatef(fmaf(cf, r,  cm));
    g  = __saturatef(fmaf(cf, g,  cm));
    bl = __saturatef(fmaf(cf, bl, cm));
    // saturation blend with per-pixel gray
    float gray = 0.299f*r + 0.587f*g + 0.114f*bl;
    float sg = (1.0f - sf)*gray;
    r  = __saturatef(fmaf(sf, r,  sg));
    g  = __saturatef(fmaf(sf, g,  sg));
    bl = __saturatef(fmaf(sf, bl, sg));
    // hue rotate (RGB -> HSV -> shift -> RGB)
    float maxc = fmaxf(fmaxf(r,g),bl);
    float minc = fminf(fminf(r,g),bl);
    float v = maxc;
    float cr = maxc - minc;
    bool  eqc = (cr == 0.0f);
    float s = cr / (eqc ? 1.0f : maxc);
    float crd = eqc ? 1.0f : cr;
    float inv = 1.0f / crd;
    float rc = (maxc - r)*inv;
    float gc = (maxc - g)*inv;
    float bc = (maxc - bl)*inv;
    float h;
    if (maxc == r)      h = bc - gc;
    else if (maxc == g) h = 2.0f + rc - bc;
    else                h = 4.0f + gc - rc;
    h = h*(1.0f/6.0f) + 1.0f;
    h = h - floorf(h);
    h = h + hue;
    h = h - floorf(h);
    float h6 = h*6.0f;
    float fi = floorf(h6);
    float f  = h6 - fi;
    int   i  = ((int)fi) % 6;   // handles the h==1.0 rounding edge
    float p = v*(1.0f - s);
    float q = v*(1.0f - s*f);
    float t = v*(1.0f - s*(1.0f - f));
    float r2 = (i==0) ? v : (i==1) ? q : (i==2||i==3) ? p : (i==4) ? t : v;
    float g2 = (i==0) ? t : (i==1||i==2) ? v : (i==3) ? q : p;
    float b2 = (i==0||i==1) ? p : (i==2) ? t : (i==3||i==4) ? v : q;
    r  = __saturatef(r2);
    g  = __saturatef(g2);
    bl = __saturatef(b2);
}

// ---------------- Kernel 2: fused jitter + crop-resize ----------------
__global__ void __launch_bounds__(256, 6) aug_kernel(const float* __restrict__ img,
                                                  const float* __restrict__ u_jitter,
                                                  const float* __restrict__ u_bright,
                                                  const float* __restrict__ u_contrast,
                                                  const float* __restrict__ u_sat,
                                                  const float* __restrict__ u_hue,
                                                  const float* __restrict__ u_crop,
                                                  const float* __restrict__ u_scale,
                                                  const float* __restrict__ u_top,
                                                  const float* __restrict__ u_left,
                                                  float* __restrict__ out)
{
    __shared__ float sm[3][SRC_ROWS][WW];   // 24192 B

    int b   = blockIdx.y;
    int ty0 = blockIdx.x * TILE_ROWS;

    bool jit = (u_jitter[b] < 0.8f);
    bool crp = (u_crop[b]   < 0.5f);

    float bf = 1.0f + (2.0f*u_bright[b]   - 1.0f)*0.2f;
    float cf = 1.0f + (2.0f*u_contrast[b] - 1.0f)*0.2f;
    float sf = 1.0f + (2.0f*u_sat[b]      - 1.0f)*0.2f;
    float hf = (2.0f*u_hue[b] - 1.0f)*0.05f;
    float mg = 0.0f;
    if (jit) {
        float acc = 0.0f;
        #pragma unroll
        for (int k = 0; k < PARTS; k++) acc += g_partial[b*PARTS+k];
        mg = acc * (1.0f/(float)HW);
    }

    const float* src = img + (size_t)b*3*HW;
    float*       dst = out + (size_t)b*3*HW;

    if (!crp) {
        // output = jittered (or raw) input rows, identity geometry
        const float4* s4 = (const float4*)src;
        float4*       d4 = (float4*)dst;
        if (!jit) {
            #pragma unroll
            for (int c = 0; c < 3; c++) {
                int base = (c*HW + ty0*WW) >> 2;
                for (int i = threadIdx.x; i < (TILE_ROWS*WW)>>2; i += blockDim.x)
                    d4[base+i] = s4[base+i];
            }
        } else {
            int base = (ty0*WW) >> 2;
            for (int i = threadIdx.x; i < (TILE_ROWS*WW)>>2; i += blockDim.x) {
                int p = base + i;
                float4 r4 = s4[p];
                float4 g4 = s4[(HW>>2)+p];
                float4 b4 = s4[(2*(HW>>2))+p];
                #pragma unroll
                for (int j = 0; j < 4; j++) {
                    float r  = ((const float*)&r4)[j];
                    float g  = ((const float*)&g4)[j];
                    float bl = ((const float*)&b4)[j];
                    jitter_px(r,g,bl, bf,cf,sf,mg,hf);
                    ((float*)&r4)[j] = r; ((float*)&g4)[j] = g; ((float*)&b4)[j] = bl;
                }
                d4[p] = r4;
                d4[(HW>>2)+p] = g4;
                d4[(2*(HW>>2))+p] = b4;
            }
        }
        return;
    }

    // ---- crop geometry: must match JAX fp32 op-for-op (floor decisions) ----
    float scale = __fadd_rn(0.85f, __fmul_rn((1.0f - 0.85f), u_scale[b]));
    float chf   = floorf(__fmul_rn(224.0f, scale));
    float cwf   = chf;   // H == W
    float hm    = __fadd_rn(__fsub_rn(224.0f, chf), 1.0f);
    float topf  = fminf(fmaxf(floorf(__fmul_rn(u_top[b],  hm)), 0.0f), 224.0f - chf);
    float leftf = fminf(fmaxf(floorf(__fmul_rn(u_left[b], hm)), 0.0f), 224.0f - cwf);

    const float inv224 = 1.0f/224.0f;

    // source row window for this tile (ys monotone in y; same formula as loop below)
    float ys0 = fminf(fmaxf(topf + ((float)ty0 + 0.5f)*chf*inv224 - 0.5f, 0.0f), 223.0f);
    int ry0 = (int)floorf(ys0);

    // ---- phase 1: load + jitter SRC_ROWS x 224 slab into smem ----
    for (int idx = threadIdx.x; idx < SRC_ROWS*WW; idx += blockDim.x) {
        int row = idx / WW;
        int col = idx - row*WW;
        int srow = min(ry0 + row, HH-1);
        int p = srow*WW + col;
        float r = src[p], g = src[HW+p], bl = src[2*HW+p];
        if (jit) jitter_px(r,g,bl, bf,cf,sf,mg,hf);
        sm[0][row][col] = r;
        sm[1][row][col] = g;
        sm[2][row][col] = bl;
    }
    __syncthreads();

    // ---- phase 2: bilinear sample TILE_ROWS x 224 output, 4 px per thread ----
    for (int idx = threadIdx.x; idx < TILE_ROWS*W4; idx += blockDim.x) {
        int ry = idx / W4;
        int c4 = idx - ry*W4;
        int oy = ty0 + ry;
        float ys = fminf(fmaxf(topf + ((float)oy + 0.5f)*chf*inv224 - 0.5f, 0.0f), 223.0f);
        float y0f = floorf(ys);
        float wy  = ys - y0f;
        int y0 = (int)y0f - ry0;
        int y1 = min((int)y0f + 1, HH-1) - ry0;

        int   x0[4], x1[4];
        float wx[4];
        #pragma unroll
        for (int j = 0; j < 4; j++) {
            int ox = c4*4 + j;
            float xs = fminf(fmaxf(leftf + ((float)ox + 0.5f)*cwf*inv224 - 0.5f, 0.0f), 223.0f);
            float x0f = floorf(xs);
            wx[j] = xs - x0f;
            x0[j] = (int)x0f;
            x1[j] = min(x0[j] + 1, WW-1);
        }

        float4* d4 = (float4*)dst;
        int po4 = oy*W4 + c4;
        #pragma unroll
        for (int c = 0; c < 3; c++) {
            float4 o;
            #pragma unroll
            for (int j = 0; j < 4; j++) {
                float a  = sm[c][y0][x0[j]], bq = sm[c][y0][x1[j]];
                float cq = sm[c][y1][x0[j]], dq = sm[c][y1][x1[j]];
                float row0 = fmaf(wx[j], bq - a,  a);
                float row1 = fmaf(wx[j], dq - cq, cq);
                ((float*)&o)[j] = fmaf(wy, row1 - row0, row0);
            }
            d4[c*(HW>>2) + po4] = o;
        }
    }
}

extern "C" void kernel_launch(void* const* d_in, const int* in_sizes, int n_in,
                              void* d_out, int out_size)
{
    const float* img        = (const float*)d_in[0];
    const float* u_jitter   = (const float*)d_in[1];
    const float* u_bright   = (const float*)d_in[2];
    const float* u_contrast = (const float*)d_in[3];
    const float* u_sat      = (const float*)d_in[4];
    const float* u_hue      = (const float*)d_in[5];
    const float* u_crop     = (const float*)d_in[6];
    const float* u_scale    = (const float*)d_in[7];
    const float* u_top      = (const float*)d_in[8];
    const float* u_left     = (const float*)d_in[9];
    float* out = (float*)d_out;

    dim3 g1(PARTS, BB);
    mean_kernel<<<g1, 256>>>(img, u_jitter, u_bright);

    dim3 g2(NTILES, BB);
    aug_kernel<<<g2, 256>>>(img, u_jitter, u_bright, u_contrast, u_sat, u_hue,
                            u_crop, u_scale, u_top, u_left, out);
}

// round 8
// speedup vs baseline: 1.5676x; 1.2084x over previous
#include <cuda_runtime.h>

#define BB 256
#define HH 224
#define WW 224
#define HW (HH*WW)          // 50176
#define W4 (WW/4)           // 56
#define PARTS 14
#define ROWS_PER_PART (HH/PARTS)   // 16
#define TILE_ROWS 8
#define SRC_ROWS 9
#define NTILES (HH/TILE_ROWS)      // 28

__device__ float g_partial[BB*PARTS];

// ---------------- Kernel 1: per-image mean of grayscale(clip(bf*img)) ----------------
__global__ void __launch_bounds__(256) mean_kernel(const float* __restrict__ img,
                                                   const float* __restrict__ u_jitter,
                                                   const float* __restrict__ u_bright)
{
    int b = blockIdx.y;
    int part = blockIdx.x;
    __shared__ float red[256];
    if (u_jitter[b] >= 0.8f) {           // mean unused for jitter-off images
        if (threadIdx.x == 0) g_partial[b*PARTS+part] = 0.0f;
        return;
    }
    float bf = 1.0f + (2.0f*u_bright[b] - 1.0f)*0.2f;
    const float4* base = (const float4*)(img + (size_t)b*3*HW);
    int p0 = (part*ROWS_PER_PART*WW) >> 2;
    const int N4 = (ROWS_PER_PART*WW) >> 2;   // 896
    float sum = 0.0f;
    for (int i = threadIdx.x; i < N4; i += blockDim.x) {
        int p = p0 + i;
        float4 r4 = base[p];
        float4 g4 = base[(HW>>2)+p];
        float4 b4 = base[(2*(HW>>2))+p];
        #pragma unroll
        for (int j = 0; j < 4; j++) {
            float r  = __saturatef(bf*((const float*)&r4)[j]);
            float g  = __saturatef(bf*((const float*)&g4)[j]);
            float bl = __saturatef(bf*((const float*)&b4)[j]);
            sum += 0.299f*r + 0.587f*g + 0.114f*bl;
        }
    }
    // warp + smem reduce
    #pragma unroll
    for (int s = 16; s > 0; s >>= 1) sum += __shfl_xor_sync(0xffffffffu, sum, s);
    if ((threadIdx.x & 31) == 0) red[threadIdx.x >> 5] = sum;
    __syncthreads();
    if (threadIdx.x < 8) {
        float v = red[threadIdx.x];
        #pragma unroll
        for (int s = 4; s > 0; s >>= 1) v += __shfl_xor_sync(0xffu, v, s);
        if (threadIdx.x == 0) g_partial[b*PARTS+part] = v;
    }
}

// ---------------- color jitter for one pixel ----------------
__device__ __forceinline__ void jitter_px(float& r, float& g, float& bl,
                                          float bf, float cf, float sf,
                                          float mg, float hue)
{
    // brightness blend with zeros (saturate folds into the MUL)
    r = __saturatef(bf*r); g = __saturatef(bf*g); bl = __saturatef(bf*bl);
    // contrast blend with mean gray
    float cm = (1.0f - cf)*mg;
    r  = __saturatef(fmaf(cf, r,  cm));
    g  = __saturatef(fmaf(cf, g,  cm));
    bl = __saturatef(fmaf(cf, bl, cm));
    // saturation blend with per-pixel gray
    float gray = 0.299f*r + 0.587f*g + 0.114f*bl;
    float sg = (1.0f - sf)*gray;
    r  = __saturatef(fmaf(sf, r,  sg));
    g  = __saturatef(fmaf(sf, g,  sg));
    bl = __saturatef(fmaf(sf, bl, sg));
    // hue rotate: RGB -> (h, v, chroma) -> shift -> RGB (branch-free, v*s == chroma)
    float maxc = fmaxf(fmaxf(r,g),bl);
    float minc = fminf(fminf(r,g),bl);
    float v  = maxc;
    float cr = maxc - minc;
    float crd = (cr == 0.0f) ? 1.0f : cr;
    float inv = __fdividef(1.0f, crd);
    float rc = (maxc - r)*inv;
    float gc = (maxc - g)*inv;
    float bc = (maxc - bl)*inv;
    float h = (maxc == r) ? (bc - gc)
            : (maxc == g) ? (2.0f + rc - bc)
                          : (4.0f + gc - rc);
    h = h*(1.0f/6.0f) + 1.0f;
    h -= floorf(h);
    h += hue;
    h -= floorf(h);
    float h6 = h*6.0f;                      // in [0, 6)
    // out_n = v - chroma * clamp01(min(k, 4-k)),  k = (n + h6) mod 6
    float kr = 5.0f + h6; kr = (kr >= 6.0f) ? (kr - 6.0f) : kr;
    float kg = 3.0f + h6; kg = (kg >= 6.0f) ? (kg - 6.0f) : kg;
    float kb = 1.0f + h6; kb = (kb >= 6.0f) ? (kb - 6.0f) : kb;
    r  = __saturatef(fmaf(-cr, __saturatef(fminf(kr, 4.0f - kr)), v));
    g  = __saturatef(fmaf(-cr, __saturatef(fminf(kg, 4.0f - kg)), v));
    bl = __saturatef(fmaf(-cr, __saturatef(fminf(kb, 4.0f - kb)), v));
}

// ---------------- Kernel 2: fused jitter + crop-resize ----------------
__global__ void __launch_bounds__(256, 6) aug_kernel(const float* __restrict__ img,
                                                  const float* __restrict__ u_jitter,
                                                  const float* __restrict__ u_bright,
                                                  const float* __restrict__ u_contrast,
                                                  const float* __restrict__ u_sat,
                                                  const float* __restrict__ u_hue,
                                                  const float* __restrict__ u_crop,
                                                  const float* __restrict__ u_scale,
                                                  const float* __restrict__ u_top,
                                                  const float* __restrict__ u_left,
                                                  float* __restrict__ out)
{
    __shared__ float sm[3][SRC_ROWS][WW];   // 24192 B

    int b   = blockIdx.y;
    int ty0 = blockIdx.x * TILE_ROWS;

    bool jit = (u_jitter[b] < 0.8f);
    bool crp = (u_crop[b]   < 0.5f);

    float bf = 1.0f + (2.0f*u_bright[b]   - 1.0f)*0.2f;
    float cf = 1.0f + (2.0f*u_contrast[b] - 1.0f)*0.2f;
    float sf = 1.0f + (2.0f*u_sat[b]      - 1.0f)*0.2f;
    float hf = (2.0f*u_hue[b] - 1.0f)*0.05f;
    float mg = 0.0f;
    if (jit) {
        float acc = 0.0f;
        #pragma unroll
        for (int k = 0; k < PARTS; k++) acc += g_partial[b*PARTS+k];
        mg = acc * (1.0f/(float)HW);
    }

    const float* src = img + (size_t)b*3*HW;
    float*       dst = out + (size_t)b*3*HW;

    if (!crp) {
        // output = jittered (or raw) input rows, identity geometry
        const float4* s4 = (const float4*)src;
        float4*       d4 = (float4*)dst;
        if (!jit) {
            #pragma unroll
            for (int c = 0; c < 3; c++) {
                int base = (c*HW + ty0*WW) >> 2;
                for (int i = threadIdx.x; i < (TILE_ROWS*WW)>>2; i += blockDim.x)
                    d4[base+i] = s4[base+i];
            }
        } else {
            int base = (ty0*WW) >> 2;
            for (int i = threadIdx.x; i < (TILE_ROWS*WW)>>2; i += blockDim.x) {
                int p = base + i;
                float4 r4 = s4[p];
                float4 g4 = s4[(HW>>2)+p];
                float4 b4 = s4[(2*(HW>>2))+p];
                #pragma unroll
                for (int j = 0; j < 4; j++) {
                    float r  = ((const float*)&r4)[j];
                    float g  = ((const float*)&g4)[j];
                    float bl = ((const float*)&b4)[j];
                    jitter_px(r,g,bl, bf,cf,sf,mg,hf);
                    ((float*)&r4)[j] = r; ((float*)&g4)[j] = g; ((float*)&b4)[j] = bl;
                }
                d4[p] = r4;
                d4[(HW>>2)+p] = g4;
                d4[(2*(HW>>2))+p] = b4;
            }
        }
        return;
    }

    // ---- crop geometry: must match JAX fp32 op-for-op (floor decisions) ----
    float scale = __fadd_rn(0.85f, __fmul_rn((1.0f - 0.85f), u_scale[b]));
    float chf   = floorf(__fmul_rn(224.0f, scale));
    float cwf   = chf;   // H == W
    float hm    = __fadd_rn(__fsub_rn(224.0f, chf), 1.0f);
    float topf  = fminf(fmaxf(floorf(__fmul_rn(u_top[b],  hm)), 0.0f), 224.0f - chf);
    float leftf = fminf(fmaxf(floorf(__fmul_rn(u_left[b], hm)), 0.0f), 224.0f - cwf);

    const float inv224 = 1.0f/224.0f;

    // source row window for this tile (ys monotone in y; same formula as loop below)
    float ys0 = fminf(fmaxf(topf + ((float)ty0 + 0.5f)*chf*inv224 - 0.5f, 0.0f), 223.0f);
    int ry0 = (int)floorf(ys0);

    // ---- phase 1: load + jitter SRC_ROWS x 224 slab into smem ----
    for (int idx = threadIdx.x; idx < SRC_ROWS*WW; idx += blockDim.x) {
        int row = idx / WW;
        int col = idx - row*WW;
        int srow = min(ry0 + row, HH-1);
        int p = srow*WW + col;
        float r = src[p], g = src[HW+p], bl = src[2*HW+p];
        if (jit) jitter_px(r,g,bl, bf,cf,sf,mg,hf);
        sm[0][row][col] = r;
        sm[1][row][col] = g;
        sm[2][row][col] = bl;
    }
    __syncthreads();

    // ---- phase 2: bilinear sample TILE_ROWS x 224 output, 4 px per thread ----
    for (int idx = threadIdx.x; idx < TILE_ROWS*W4; idx += blockDim.x) {
        int ry = idx / W4;
        int c4 = idx - ry*W4;
        int oy = ty0 + ry;
        float ys = fminf(fmaxf(topf + ((float)oy + 0.5f)*chf*inv224 - 0.5f, 0.0f), 223.0f);
        float y0f = floorf(ys);
        float wy  = ys - y0f;
        int y0 = (int)y0f - ry0;
        int y1 = min((int)y0f + 1, HH-1) - ry0;

        int   x0[4], x1[4];
        float wx[4];
        #pragma unroll
        for (int j = 0; j < 4; j++) {
            int ox = c4*4 + j;
            float xs = fminf(fmaxf(leftf + ((float)ox + 0.5f)*cwf*inv224 - 0.5f, 0.0f), 223.0f);
            float x0f = floorf(xs);
            wx[j] = xs - x0f;
            x0[j] = (int)x0f;
            x1[j] = min(x0[j] + 1, WW-1);
        }

        float4* d4 = (float4*)dst;
        int po4 = oy*W4 + c4;
        #pragma unroll
        for (int c = 0; c < 3; c++) {
            float4 o;
            #pragma unroll
            for (int j = 0; j < 4; j++) {
                float a  = sm[c][y0][x0[j]], bq = sm[c][y0][x1[j]];
                float cq = sm[c][y1][x0[j]], dq = sm[c][y1][x1[j]];
                float row0 = fmaf(wx[j], bq - a,  a);
                float row1 = fmaf(wx[j], dq - cq, cq);
                ((float*)&o)[j] = fmaf(wy, row1 - row0, row0);
            }
            d4[c*(HW>>2) + po4] = o;
        }
    }
}

extern "C" void kernel_launch(void* const* d_in, const int* in_sizes, int n_in,
                              void* d_out, int out_size)
{
    const float* img        = (const float*)d_in[0];
    const float* u_jitter   = (const float*)d_in[1];
    const float* u_bright   = (const float*)d_in[2];
    const float* u_contrast = (const float*)d_in[3];
    const float* u_sat      = (const float*)d_in[4];
    const float* u_hue      = (const float*)d_in[5];
    const float* u_crop     = (const float*)d_in[6];
    const float* u_scale    = (const float*)d_in[7];
    const float* u_top      = (const float*)d_in[8];
    const float* u_left     = (const float*)d_in[9];
    float* out = (float*)d_out;

    dim3 g1(PARTS, BB);
    mean_kernel<<<g1, 256>>>(img, u_jitter, u_bright);

    dim3 g2(NTILES, BB);
    aug_kernel<<<g2, 256>>>(img, u_jitter, u_bright, u_contrast, u_sat, u_hue,
                            u_crop, u_scale, u_top, u_left, out);
}